// round 4
// baseline (speedup 1.0000x reference)
#include <cuda_runtime.h>
#include <math.h>

// Problem constants (fixed shapes from reference setup_inputs)
#define NB   8
#define ND   768
#define NCH  3
#define NMIX 5
#define NH   10
#define NS   10

#define PI2f      6.2831853071795864769f
#define ZITTERf   1e-4f
#define GEPSf     1e-20f

#define T_TILES  24          // ND/32
#define NGRP     6           // groups of 4 column-tiles
#define NPAIR    300         // 24*25/2 upper-tri tile pairs (k3)
#define NSLOT    30          // 24 j-slots + 6 group i-slots

// Scratch (device globals: allocation is forbidden)
__device__ float g_featp[NSLOT][NB * ND * NCH * NMIX];  // exclusive partial features
__device__ float g_hpart[NB][T_TILES][NCH * NH];        // k2a partial relu-sums
__device__ float g_w[NB * NCH * NMIX];                  // mixture weights

// ---------------------------------------------------------------------------
// Kernel 1 (symmetric): feat[b,i,c,m] = sum_j K_m(x_i-x_j) * y_j
// Strip block: row-tile ti (32 rows) x column-group g (4 tiles of 32).
// Double-buffered j-part reduce: ONE __syncthreads per tile; the 160-thread
// reduce overlaps the next tile's MUFU burst.
// grid (24*6, NB*NCH), block (32,8).
// ---------------------------------------------------------------------------
__global__ __launch_bounds__(256) void k1_feature_sym(
    const float* __restrict__ xc, const float* __restrict__ yc,
    const float* __restrict__ mu, const float* __restrict__ inv_std)
{
    const int ti = blockIdx.x / NGRP;
    const int g  = blockIdx.x % NGRP;
    if (ti > 4 * g + 3) return;               // strip fully below diagonal
    const int bc = blockIdx.y;
    const int b = bc / NCH, c = bc % NCH;

    const int tx = threadIdx.x;               // lane = j within tile
    const int ty = threadIdx.y;               // warp id
    const int tid = ty * 32 + tx;

    __shared__ float sxi[32], syi[32];
    __shared__ float sxj[128], syj[128];
    __shared__ float sj[2][8][160];
    __shared__ int   sjt[2];                  // which tj each buffer holds

    if (tid < 32) {
        sxi[tid] = xc[(b * ND + ti * 32 + tid) * NCH + c];
        syi[tid] = yc[(b * ND + ti * 32 + tid) * NCH + c];
    }
    {
        const int j0 = g * 128;
        if (tid < 128) {
            sxj[tid] = xc[(b * ND + j0 + tid) * NCH + c];
            syj[tid] = yc[(b * ND + j0 + tid) * NCH + c];
        }
    }
    __syncthreads();

    float nA[NMIX], wm[NMIX];
#pragma unroll
    for (int m = 0; m < NMIX; ++m) {
        float s = __ldg(&inv_std[m]);
        nA[m] = -0.5f * PI2f * PI2f * s * s;
        wm[m] = PI2f * __ldg(&mu[m]);
    }

    float xir[4], yir[4];
#pragma unroll
    for (int r = 0; r < 4; ++r) { xir[r] = sxi[ty + 8 * r]; yir[r] = syi[ty + 8 * r]; }

    float acc_i[4][NMIX];
#pragma unroll
    for (int r = 0; r < 4; ++r)
#pragma unroll
        for (int m = 0; m < NMIX; ++m) acc_i[r][m] = 0.f;

    int buf = 0;
    for (int tjl = 0; tjl < 4; ++tjl) {
        const int tj = g * 4 + tjl;
        if (tj < ti) continue;                // uniform branch
        const float xjv = sxj[tjl * 32 + tx];
        const float yjv = syj[tjl * 32 + tx];
        float accjp[NMIX] = {0.f, 0.f, 0.f, 0.f, 0.f};

#pragma unroll
        for (int r = 0; r < 4; ++r) {
            float d  = xir[r] - xjv;
            float d2 = d * d;
#pragma unroll
            for (int m = 0; m < NMIX; ++m) {
                float e  = __expf(nA[m] * d2);
                float cs = __cosf(wm[m] * d);
                float kv = e * cs;
                acc_i[r][m] = fmaf(kv, yjv, acc_i[r][m]);
                accjp[m]    = fmaf(kv, yir[r], accjp[m]);
            }
        }

        if (tj != ti) {                       // j-part -> slot ti (deferred reduce)
#pragma unroll
            for (int m = 0; m < NMIX; ++m) sj[buf][ty][tx * 5 + m] = accjp[m];
            if (tid == 0) sjt[buf] = tj;
            __syncthreads();
            if (tid < 160) {
                float s = 0.f;
#pragma unroll
                for (int w = 0; w < 8; ++w) s += sj[buf][w][tid];
                int jl = tid / 5, m = tid % 5;
                g_featp[ti][((b * ND + sjt[buf] * 32 + jl) * NCH + c) * NMIX + m] = s;
            }
            buf ^= 1;                         // next tile writes other buffer (no 2nd sync)
        }
    }

    // i-part: lane reduce over j (32 lanes), lane 0 stores. slot 24+g
#pragma unroll
    for (int r = 0; r < 4; ++r) {
        int base = ((b * ND + ti * 32 + ty + 8 * r) * NCH + c) * NMIX;
#pragma unroll
        for (int m = 0; m < NMIX; ++m) {
            float v = acc_i[r][m];
            v += __shfl_down_sync(0xffffffffu, v, 16);
            v += __shfl_down_sync(0xffffffffu, v, 8);
            v += __shfl_down_sync(0xffffffffu, v, 4);
            v += __shfl_down_sync(0xffffffffu, v, 2);
            v += __shfl_down_sync(0xffffffffu, v, 1);
            if (tx == 0) g_featp[24 + g][base + m] = v;
        }
    }
}

// ---------------------------------------------------------------------------
// Kernel 2a: partial relu-hidden sums per 32-row tile.
// grid (24, NB), block 128 (96 active). Reads only populated slots.
// ---------------------------------------------------------------------------
__global__ __launch_bounds__(128) void k2a_hidden(
    const float* __restrict__ yc,
    const float* __restrict__ W1, const float* __restrict__ b1)
{
    const int blk = blockIdx.x;               // row tile
    const int b   = blockIdx.y;
    const int t   = threadIdx.x;

    __shared__ float spart[96][NH];

    if (t < 96) {
        const int i = blk * 32 + t / 3;
        const int c = t % 3;
        const int base = ((b * ND + i) * NCH + c) * NMIX;

        float fs[NMIX] = {0.f, 0.f, 0.f, 0.f, 0.f};
        for (int s = 0; s < blk; ++s) {
#pragma unroll
            for (int m = 0; m < NMIX; ++m) fs[m] += g_featp[s][base + m];
        }
        for (int gg = blk >> 2; gg < NGRP; ++gg) {
#pragma unroll
            for (int m = 0; m < NMIX; ++m) fs[m] += g_featp[24 + gg][base + m];
        }
        const float y = __ldg(&yc[(b * ND + i) * NCH + c]);
#pragma unroll
        for (int m = 0; m < NMIX; ++m) fs[m] += ZITTERf * y;

#pragma unroll
        for (int k = 0; k < NH; ++k) {
            float h = __ldg(&b1[k]);
#pragma unroll
            for (int m = 0; m < NMIX; ++m)
                h = fmaf(fs[m], __ldg(&W1[k * (NMIX + 1) + m]), h);
            h = fmaf(y, __ldg(&W1[k * (NMIX + 1) + NMIX]), h);
            spart[t][k] = fmaxf(h, 0.f);
        }
    }
    __syncthreads();

    if (t < NCH * NH) {                       // t = c*10 + k
        const int c = t / NH, k = t % NH;
        float s = 0.f;
#pragma unroll
        for (int r = 0; r < 32; ++r) s += spart[r * 3 + c][k];
        g_hpart[b][blk][t] = s;
    }
}

// ---------------------------------------------------------------------------
// Kernel 2b: finish mean, MLP chain, Gumbel-softmax -> g_w. grid NB, block 32.
// ---------------------------------------------------------------------------
__global__ __launch_bounds__(32) void k2b_mlp_gumbel(
    const float* __restrict__ unif,
    const float* __restrict__ W2, const float* __restrict__ b2,
    const float* __restrict__ W3, const float* __restrict__ b3,
    const float* __restrict__ W4, const float* __restrict__ b4,
    const float* __restrict__ W5, const float* __restrict__ b5)
{
    const int b = blockIdx.x;
    const int tid = threadIdx.x;

    __shared__ float sflat[NCH * NH];
    __shared__ float sh2[NH], sh3[NH], sh4[NH];
    __shared__ float sll[NCH * NMIX];
    __shared__ float sg[NS * NCH][NMIX];

    if (tid < NCH * NH) {
        float s = 0.f;
        for (int p = 0; p < T_TILES; ++p) s += g_hpart[b][p][tid];
        sflat[tid] = s * (1.0f / (float)ND);
    }
    __syncthreads();
    if (tid < NH) {
        float a = __ldg(&b2[tid]);
        for (int t = 0; t < NCH * NH; ++t) a = fmaf(sflat[t], __ldg(&W2[tid * NCH * NH + t]), a);
        sh2[tid] = fmaxf(a, 0.f);
    }
    __syncthreads();
    if (tid < NH) {
        float a = __ldg(&b3[tid]);
        for (int t = 0; t < NH; ++t) a = fmaf(sh2[t], __ldg(&W3[tid * NH + t]), a);
        sh3[tid] = fmaxf(a, 0.f);
    }
    __syncthreads();
    if (tid < NH) {
        float a = __ldg(&b4[tid]);
        for (int t = 0; t < NH; ++t) a = fmaf(sh3[t], __ldg(&W4[tid * NH + t]), a);
        sh4[tid] = fmaxf(a, 0.f);
    }
    __syncthreads();
    if (tid < NCH * NMIX) {
        float a = __ldg(&b5[tid]);
        for (int k = 0; k < NH; ++k) a = fmaf(sh4[k], __ldg(&W5[tid * NH + k]), a);
        sll[tid] = a;
    }
    __syncthreads();

    if (tid < NS * NCH) {                     // tid = s*3 + c
        const int s = tid / NCH, c = tid % NCH;
        float z[NMIX], zm = -1e30f;
#pragma unroll
        for (int m = 0; m < NMIX; ++m) {
            float u = __ldg(&unif[((b * NS + s) * NCH + c) * NMIX + m]);
            float gb = -__logf(-__logf(u + GEPSf));
            z[m] = (gb + sll[c * NMIX + m]) * 10.0f;   // /TEMP, TEMP=0.1
            zm = fmaxf(zm, z[m]);
        }
        float e[NMIX], sum = 0.f;
#pragma unroll
        for (int m = 0; m < NMIX; ++m) { e[m] = __expf(z[m] - zm); sum += e[m]; }
        float inv = 1.0f / (sum * (float)NS);          // fold mean over ns
#pragma unroll
        for (int m = 0; m < NMIX; ++m) sg[tid][m] = e[m] * inv;
    }
    __syncthreads();
    if (tid < NCH * NMIX) {                   // tid = c*5 + m
        const int c = tid / NMIX, m = tid % NMIX;
        float w = 0.f;
#pragma unroll
        for (int s = 0; s < NS; ++s) w += sg[s * NCH + c][m];
        g_w[b * NCH * NMIX + tid] = w;
    }
}

// ---------------------------------------------------------------------------
// Kernel 3: out[b,i,j,c] = sum_m w[b,c,m] * K_m(d) + (i==j) diag[c]
// Upper-triangle pair decode; fully vectorized float4 I/O.
// Each thread produces 4 consecutive floats of an output row (j,c flattened),
// STG.128 direct from regs + STS.128 to tile; mirror = scalar shared gather
// packed into float4 stores. grid (300, NB), block 256.
// ---------------------------------------------------------------------------
#define TPADF 100   // tile row stride in floats (400B, 16B-aligned rows)

__global__ __launch_bounds__(256) void k3_weighted(
    const float* __restrict__ xc, const float* __restrict__ mu,
    const float* __restrict__ inv_std, const float* __restrict__ likerr,
    float* __restrict__ out)
{
    // decode upper-tri pair (ti <= tj)
    int p = blockIdx.x;
    int ti = 0, rem = T_TILES;
    while (p >= rem) { p -= rem; ++ti; --rem; }
    const int tj = ti + p;

    const int b = blockIdx.y;
    const int i0 = ti * 32, j0 = tj * 32;
    const int tid = threadIdx.x;

    __shared__ float sxi[96], sxj[96];        // [row*3 + c], contiguous copy of xc rows
    __shared__ float swv[NCH * NMIX], snA[NMIX], swm[NMIX], sdiag[NCH];
    __shared__ float tile[32][TPADF];

    if (tid < 96)       sxi[tid]      = xc[(b * ND + i0) * NCH + tid];
    else if (tid < 192) sxj[tid - 96] = xc[(b * ND + j0) * NCH + (tid - 96)];
    if (tid < NCH * NMIX) swv[tid] = g_w[b * NCH * NMIX + tid];
    if (tid < NMIX) {
        float s = inv_std[tid];
        snA[tid] = -0.5f * PI2f * PI2f * s * s;
        swm[tid] = PI2f * mu[tid];
    }
    if (tid < NCH) {
        float l = fminf(fmaxf(likerr[tid], 0.1f), 1.0f);
        sdiag[tid] = ZITTERf + l * l;
    }
    __syncthreads();

    const bool offdiag = (ti != tj);

    // compute: 768 float4 chunks (32 rows x 24 chunks), 3 per thread
#pragma unroll
    for (int it = 0; it < 3; ++it) {
        const int q  = tid + it * 256;
        const int i  = q / 24;                // local row
        const int f0 = (q % 24) * 4;          // float offset in row (j,c flattened)

        const float xi0 = sxi[i * 3 + 0];
        const float xi1 = sxi[i * 3 + 1];
        const float xi2 = sxi[i * 3 + 2];
        const float4 xjv = *reinterpret_cast<const float4*>(&sxj[f0]);
        const float xj_[4] = {xjv.x, xjv.y, xjv.z, xjv.w};

        float v[4];
#pragma unroll
        for (int t = 0; t < 4; ++t) {
            const int f = f0 + t;
            const int j = f / 3;
            const int c = f - 3 * j;
            const float xi = (c == 0) ? xi0 : ((c == 1) ? xi1 : xi2);
            const float d  = xi - xj_[t];
            const float d2 = d * d;
            float acc = 0.f;
#pragma unroll
            for (int m = 0; m < NMIX; ++m) {
                float e  = __expf(snA[m] * d2);
                float cs = __cosf(swm[m] * d);
                acc = fmaf(swv[c * NMIX + m], e * cs, acc);
            }
            if (i0 + i == j0 + j) acc += sdiag[c];
            v[t] = acc;
        }
        float4 vv = make_float4(v[0], v[1], v[2], v[3]);
        *reinterpret_cast<float4*>(&out[((size_t)(b * ND + i0 + i) * ND + j0) * NCH + f0]) = vv;
        if (offdiag)
            *reinterpret_cast<float4*>(&tile[i][f0]) = vv;
    }

    // mirror: out[b, j0+jj, i0+i, c] = tile[i][jj*3+c]
    if (offdiag) {
        __syncthreads();
#pragma unroll
        for (int it = 0; it < 3; ++it) {
            const int q  = tid + it * 256;
            const int jj = q / 24;
            const int f0 = (q % 24) * 4;
            float v[4];
#pragma unroll
            for (int t = 0; t < 4; ++t) {
                const int f = f0 + t;
                const int i = f / 3;
                const int c = f - 3 * i;
                v[t] = tile[i][jj * 3 + c];
            }
            *reinterpret_cast<float4*>(&out[((size_t)(b * ND + j0 + jj) * ND + i0) * NCH + f0]) =
                make_float4(v[0], v[1], v[2], v[3]);
        }
    }
}

// ---------------------------------------------------------------------------
// Launch. Input order: xc, yc, mu, inv_std, likerr, unif, W1..b5
// ---------------------------------------------------------------------------
extern "C" void kernel_launch(void* const* d_in, const int* in_sizes, int n_in,
                              void* d_out, int out_size)
{
    const float* xc      = (const float*)d_in[0];
    const float* yc      = (const float*)d_in[1];
    const float* mu      = (const float*)d_in[2];
    const float* inv_std = (const float*)d_in[3];
    const float* likerr  = (const float*)d_in[4];
    const float* unif    = (const float*)d_in[5];
    const float* W1 = (const float*)d_in[6];  const float* b1 = (const float*)d_in[7];
    const float* W2 = (const float*)d_in[8];  const float* b2 = (const float*)d_in[9];
    const float* W3 = (const float*)d_in[10]; const float* b3 = (const float*)d_in[11];
    const float* W4 = (const float*)d_in[12]; const float* b4 = (const float*)d_in[13];
    const float* W5 = (const float*)d_in[14]; const float* b5 = (const float*)d_in[15];
    float* out = (float*)d_out;

    dim3 g1(T_TILES * NGRP, NB * NCH);
    dim3 t1(32, 8);
    k1_feature_sym<<<g1, t1>>>(xc, yc, mu, inv_std);

    dim3 g2a(T_TILES, NB);
    k2a_hidden<<<g2a, 128>>>(yc, W1, b1);

    k2b_mlp_gumbel<<<NB, 32>>>(unif, W2, b2, W3, b3, W4, b4, W5, b5);

    dim3 g3(NPAIR, NB);
    k3_weighted<<<g3, 256>>>(xc, mu, inv_std, likerr, out);
}